// round 1
// baseline (speedup 1.0000x reference)
#include <cuda_runtime.h>
#include <math.h>

#define B_   2
#define P_   8192
#define NB_  24
#define C1_  32
#define C2_  32
#define K_   13
#define A_   12
#define CA_  384            // c1 * A
#define NDR_ 384            // C2 * A (n = r*32 + d)
#define TP_  32             // points per block
#define CC_  32             // ca chunk
#define NCH_ 12             // CA_/CC_
#define STEPS_ (K_*NCH_)    // 156

// -------- device scratch (no allocations allowed) --------
__device__ __align__(16) float g_WT[K_*CA_*NDR_];   // [k][ca][r*32+d]  (~7.7MB)
__device__ __align__(16) float g_md[B_*P_*3];       // mean_dir
__device__ __align__(16) float g_kpo[C2_*K_*3];     // normalized k_pos_ori
__device__ __align__(16) float g_be[C2_*A_];        // bias_eff[d][r]

// -------- prep: k_pos_ori + bias_eff --------
__global__ void prep_small(const float* __restrict__ kpw, const float* __restrict__ vs,
                           const int* __restrict__ idx_map, const float* __restrict__ bias,
                           const int* __restrict__ lvl, const int* __restrict__ tivr) {
    int tid = threadIdx.x;
    if (tid < C2_*K_) {
        int d = tid / K_, k = tid % K_;
        float s0 = 0.f, s1 = 0.f, s2 = 0.f;
        for (int a = 0; a < A_; a++) {
            float w = kpw[d*36 + idx_map[k*A_ + a]];
            s0 += w * vs[a*3+0];
            s1 += w * vs[a*3+1];
            s2 += w * vs[a*3+2];
        }
        float nm = sqrtf(s0*s0 + s1*s1 + s2*s2);
        float inv = 1.0f / fmaxf(nm, 1e-12f);
        g_kpo[tid*3+0] = s0*inv;
        g_kpo[tid*3+1] = s1*inv;
        g_kpo[tid*3+2] = s2*inv;
    }
    if (tid < C2_*A_) {
        int d = tid / A_, r = tid % A_;
        float be = 0.f;
        for (int k = 0; k < K_; k++) be += bias[d*5 + lvl[tivr[r*K_ + k]]];
        g_be[tid] = be;
    }
}

// -------- prep: WT[d,c,k,a,r] -> g_WT[k][c*12+a][r*32+d] --------
__global__ void prep_wt(const float* __restrict__ W, const float* __restrict__ kpw,
                        const int* __restrict__ idx_map, const int* __restrict__ tivr,
                        const int* __restrict__ tir) {
    int idx = blockIdx.x * blockDim.x + threadIdx.x;
    if (idx >= K_*CA_*NDR_) return;
    int k   = idx / (CA_*NDR_);
    int rem = idx - k*(CA_*NDR_);
    int ca  = rem / NDR_;
    int n   = rem - ca*NDR_;
    int c = ca / A_, a = ca - c*A_;
    int r = n >> 5, d = n & 31;
    int m = idx_map[tivr[r*K_ + k]*A_ + tir[r*A_ + a]];
    g_WT[idx] = W[(d*C1_ + c)*36 + m] * kpw[d*36 + m];
}

// -------- prep: mean of normalized neighbor directions --------
__global__ void mean_dir_kernel(const int* __restrict__ nbr, const float* __restrict__ vert) {
    int t = blockIdx.x * blockDim.x + threadIdx.x;
    if (t >= B_*P_) return;
    int b = t / P_;
    float vx = vert[t*3+0], vy = vert[t*3+1], vz = vert[t*3+2];
    float mx = 0.f, my = 0.f, mz = 0.f;
    const int* np = nbr + (size_t)t * NB_;
    const float* vb = vert + (size_t)b * P_ * 3;
    #pragma unroll 4
    for (int n = 0; n < NB_; n++) {
        int q = np[n];
        float dx = vb[q*3+0] - vx;
        float dy = vb[q*3+1] - vy;
        float dz = vb[q*3+2] - vz;
        float nm = sqrtf(dx*dx + dy*dy + dz*dz);
        float inv = 1.0f / fmaxf(nm, 1e-12f);
        mx += dx*inv; my += dy*inv; mz += dz*inv;
    }
    const float s = 1.0f / (float)NB_;
    g_md[t*3+0] = mx*s; g_md[t*3+1] = my*s; g_md[t*3+2] = mz*s;
}

// -------- cp.async helper --------
__device__ __forceinline__ void cp16(float* dst, const float* src) {
    unsigned a = (unsigned)__cvta_generic_to_shared(dst);
    asm volatile("cp.async.cg.shared.global [%0], [%1], 16;" :: "r"(a), "l"(src));
}

// -------- main fused kernel --------
// grid = 512 (b * 256 p-tiles), block = 256 threads.
// thread (d = tid&31, gp = tid>>5) computes 4 points x 12 r for its d.
__global__ void __launch_bounds__(256, 1)
main_kernel(const float* __restrict__ fm, float* __restrict__ out) {
    extern __shared__ float sm[];
    float* sFM  = sm;                       // [2][TP_][CA_]   96KB, row = point (1536B)
    float* sB   = sm + 2*TP_*CA_;           // [2][CC_][NDR_]  96KB
    float* sKPO = sB + 2*CC_*NDR_;          // [C2_*K_*3]

    const int tid = threadIdx.x;
    const int d   = tid & 31;
    const int gp  = tid >> 5;               // warp id = p-group
    const int b   = blockIdx.x >> 8;        // 256 p-tiles per batch
    const int p0  = (blockIdx.x & 255) * TP_;
    const float* fmB = fm + (size_t)b * C1_ * K_ * P_ * A_;

    for (int i = tid; i < C2_*K_*3; i += 256) sKPO[i] = g_kpo[i];

    float md[4][3];
    #pragma unroll
    for (int i = 0; i < 4; i++) {
        int p = p0 + 4*gp + i;
        const float* mp = g_md + ((size_t)b*P_ + p)*3;
        md[i][0] = mp[0]; md[i][1] = mp[1]; md[i][2] = mp[2];
    }

    float acc[4][12];
    #pragma unroll
    for (int i = 0; i < 4; i++)
        #pragma unroll
        for (int r = 0; r < 12; r++) acc[i][r] = 0.f;

    // loaders: fm tile (32 pts x 384 ca) and WT chunk (32 ca x 384 n)
    auto fm_load = [&](int k, int buf) {
        float* base = sFM + buf*TP_*CA_;
        #pragma unroll
        for (int j = 0; j < 12; j++) {
            int t  = tid + 256*j;              // 0..3071 16B-chunks
            int c  = t / 96;                   // 96 chunks per c (32 pp x 3 aq)
            int rm = t - c*96;
            int pp = rm / 3;
            int aq = rm - pp*3;
            const float* src = fmB + ((size_t)(c*K_ + k)*P_ + (p0 + pp))*A_ + aq*4;
            cp16(base + pp*CA_ + c*A_ + aq*4, src);
        }
    };
    auto b_load = [&](int k, int cc, int buf) {
        const float* src = g_WT + ((size_t)k*CA_ + cc*CC_)*NDR_;
        float* dst = sB + buf*CC_*NDR_;
        #pragma unroll
        for (int j = 0; j < 12; j++) {
            int t = (tid + 256*j) * 4;
            cp16(dst + t, src + t);
        }
    };

    __syncthreads();                           // sKPO visible

    fm_load(0, 0);
    b_load(0, 0, 0);
    asm volatile("cp.async.commit_group;" ::: "memory");

    int s = 0;
    for (int k = 0; k < K_; k++) {
        const float* kp = sKPO + (d*K_ + k)*3;
        float pwv[4];
        #pragma unroll
        for (int i = 0; i < 4; i++) {
            float v = md[i][0]*kp[0] + md[i][1]*kp[1] + md[i][2]*kp[2];
            pwv[i] = fmaxf(v, 0.0f);
        }
        float part[4][12];
        #pragma unroll
        for (int i = 0; i < 4; i++)
            #pragma unroll
            for (int r = 0; r < 12; r++) part[i][r] = 0.f;

        const int fbuf = k & 1;
        for (int cc = 0; cc < NCH_; cc++) {
            asm volatile("cp.async.wait_group 0;" ::: "memory");
            __syncthreads();

            const int ns = s + 1;
            if (ns < STEPS_) {
                const int nk  = ns / NCH_;
                const int ncc = ns - nk*NCH_;
                b_load(nk, ncc, ns & 1);
                if (ncc == 0) fm_load(nk, nk & 1);
            }
            asm volatile("cp.async.commit_group;" ::: "memory");

            const float* Af = sFM + fbuf*TP_*CA_ + (4*gp)*CA_ + cc*CC_;  // broadcast reads
            const float* Bf = sB  + (s & 1)*CC_*NDR_ + d;                // lane-consecutive

            #pragma unroll 8
            for (int i = 0; i < CC_; i++) {
                float a0 = Af[i];
                float a1 = Af[CA_ + i];
                float a2 = Af[2*CA_ + i];
                float a3 = Af[3*CA_ + i];
                const float* br = Bf + i*NDR_;
                #pragma unroll
                for (int r = 0; r < 12; r++) {
                    float bv = br[r*32];
                    part[0][r] = fmaf(a0, bv, part[0][r]);
                    part[1][r] = fmaf(a1, bv, part[1][r]);
                    part[2][r] = fmaf(a2, bv, part[2][r]);
                    part[3][r] = fmaf(a3, bv, part[3][r]);
                }
            }
            s++;
        }
        #pragma unroll
        for (int i = 0; i < 4; i++)
            #pragma unroll
            for (int r = 0; r < 12; r++)
                acc[i][r] = fmaf(pwv[i], part[i][r], acc[i][r]);
    }

    // epilogue: relu(acc + bias_eff), coalesced-ish float4 stores
    float be[12];
    #pragma unroll
    for (int r = 0; r < 12; r++) be[r] = g_be[d*A_ + r];

    #pragma unroll
    for (int i = 0; i < 4; i++) {
        int p = p0 + 4*gp + i;
        float* op = out + ((size_t)(b*C2_ + d)*P_ + p) * A_;
        float v[12];
        #pragma unroll
        for (int r = 0; r < 12; r++) v[r] = fmaxf(acc[i][r] + be[r], 0.0f);
        reinterpret_cast<float4*>(op)[0] = make_float4(v[0], v[1], v[2],  v[3]);
        reinterpret_cast<float4*>(op)[1] = make_float4(v[4], v[5], v[6],  v[7]);
        reinterpret_cast<float4*>(op)[2] = make_float4(v[8], v[9], v[10], v[11]);
    }
}

// -------- launcher --------
extern "C" void kernel_launch(void* const* d_in, const int* in_sizes, int n_in,
                              void* d_out, int out_size) {
    const int*   nbr     = (const int*)  d_in[0];   // (B,P,24)
    const float* vert    = (const float*)d_in[1];   // (B,P,3)
    const float* fm      = (const float*)d_in[2];   // (B,C1,K,P,A)
    const float* W       = (const float*)d_in[3];   // (C2,C1,36)
    const float* bias    = (const float*)d_in[4];   // (C2,5)
    const float* kpw     = (const float*)d_in[5];   // (C2,36)
    const float* vs      = (const float*)d_in[6];   // (12,3)
    const int*   idx_map = (const int*)  d_in[7];   // (156,)
    const int*   tivr    = (const int*)  d_in[8];   // (A,K)
    const int*   tir     = (const int*)  d_in[9];   // (A,A)
    const int*   lvl     = (const int*)  d_in[10];  // (13,)
    float*       out     = (float*)d_out;           // (B,C2,P,A)

    prep_small<<<1, 512>>>(kpw, vs, idx_map, bias, lvl, tivr);

    int wt_elems = K_*CA_*NDR_;
    prep_wt<<<(wt_elems + 255)/256, 256>>>(W, kpw, idx_map, tivr, tir);

    mean_dir_kernel<<<(B_*P_ + 255)/256, 256>>>(nbr, vert);

    const int smem_bytes = (2*TP_*CA_ + 2*CC_*NDR_ + C2_*K_*3) * (int)sizeof(float); // ~197KB
    cudaFuncSetAttribute(main_kernel, cudaFuncAttributeMaxDynamicSharedMemorySize, smem_bytes);
    main_kernel<<<B_ * (P_/TP_), 256, smem_bytes>>>(fm, out);
}